// round 2
// baseline (speedup 1.0000x reference)
#include <cuda_runtime.h>
#include <math.h>

#define NN 50000
#define NE 800000
#define HD 128
#define NL 4

// scratch (allocation-free rule: __device__ globals)
__device__ float g_h[NN * HD];
__device__ float g_A[NN * HD];
__device__ float g_B[NN * HD];
__device__ float g_G[NN * HD];
__device__ float g_agg[NN * HD];
__device__ float g_tmp[NN * HD];
__device__ float g_deg[NN];

__device__ __forceinline__ float gelu_f(float x) {
    return 0.5f * x * (1.0f + erff(x * 0.70710678118654752440f));
}

__device__ __forceinline__ void red_add_v4(float* addr, float x, float y, float z, float w) {
    asm volatile("red.global.add.v4.f32 [%0], {%1, %2, %3, %4};"
                 :: "l"(addr), "f"(x), "f"(y), "f"(z), "f"(w) : "memory");
}

// ---------------------------------------------------------------------------
// Warp-cooperative GEMM tile: each warp computes 4 nodes x 128 outputs.
// lane handles output columns j0..j0+3 (j0 = lane*4).
// sW: [K][128] row-major in smem. sX: 4 rows of K floats (warp-private smem).
// ---------------------------------------------------------------------------
template <int K>
__device__ __forceinline__ void warp_gemm(const float* __restrict__ sW,
                                          const float* __restrict__ sX,
                                          int j0, float acc[4][4]) {
#pragma unroll 4
    for (int k4 = 0; k4 < K / 4; ++k4) {
        float4 xv[4];
#pragma unroll
        for (int r = 0; r < 4; ++r)
            xv[r] = *(const float4*)(sX + r * K + k4 * 4);
#pragma unroll
        for (int kk = 0; kk < 4; ++kk) {
            float4 wv = *(const float4*)(sW + (k4 * 4 + kk) * HD + j0);
#pragma unroll
            for (int r = 0; r < 4; ++r) {
                float x = ((const float*)&xv[r])[kk];
                acc[r][0] += x * wv.x;
                acc[r][1] += x * wv.y;
                acc[r][2] += x * wv.z;
                acc[r][3] += x * wv.w;
            }
        }
    }
}

// stage 4 rows of K floats from global into warp-private smem (zero-fill OOB)
template <int K>
__device__ __forceinline__ void stage4(float* sX, const float* __restrict__ gX,
                                       int n0, int lane) {
#pragma unroll
    for (int r = 0; r < 4; ++r) {
        int n = n0 + r;
#pragma unroll
        for (int c0 = 0; c0 < K; c0 += 128) {
            int c = c0 + lane * 4;
            if (c < K) {
                float4 v = (n < NN) ? *(const float4*)(gX + (size_t)n * K + c)
                                    : make_float4(0.f, 0.f, 0.f, 0.f);
                *(float4*)(sX + r * K + c) = v;
            }
        }
    }
}

// ---------------------------------------------------------------------------
// utility kernels
// ---------------------------------------------------------------------------
__global__ void zero_kernel(float* p, int n) {
    int i = blockIdx.x * blockDim.x + threadIdx.x;
    if (i < n) p[i] = 0.f;
}
__global__ void zero4_kernel(float4* p, int n4) {
    int i = blockIdx.x * blockDim.x + threadIdx.x;
    if (i < n4) p[i] = make_float4(0.f, 0.f, 0.f, 0.f);
}
__global__ void deg_kernel(const int* __restrict__ dst, float* deg) {
    int e = blockIdx.x * blockDim.x + threadIdx.x;
    if (e < NE) atomicAdd(&deg[dst[e]], 1.0f);
}

// ---------------------------------------------------------------------------
// encoder: h = gelu(x @ W1 + b1) @ W2 + b2      (x: [N,16])
// ---------------------------------------------------------------------------
__global__ __launch_bounds__(256, 2) void encode_kernel(
    const float* __restrict__ x, const float* __restrict__ W1,
    const float* __restrict__ b1, const float* __restrict__ W2,
    const float* __restrict__ b2, float* __restrict__ out) {
    extern __shared__ float sm[];
    float* sW1 = sm;                      // 16*128
    float* sW2 = sW1 + 16 * HD;           // 128*128
    float* sb1 = sW2 + HD * HD;           // 128
    float* sb2 = sb1 + HD;                // 128
    float* sXall = sb2 + HD;              // 8*4*16
    float* sHall = sXall + 8 * 4 * 16;    // 8*4*128

    for (int i = threadIdx.x; i < 16 * HD / 4; i += blockDim.x)
        ((float4*)sW1)[i] = ((const float4*)W1)[i];
    for (int i = threadIdx.x; i < HD * HD / 4; i += blockDim.x)
        ((float4*)sW2)[i] = ((const float4*)W2)[i];
    if (threadIdx.x < HD) {
        sb1[threadIdx.x] = b1[threadIdx.x];
        sb2[threadIdx.x] = b2[threadIdx.x];
    }
    __syncthreads();

    int warp = threadIdx.x >> 5, lane = threadIdx.x & 31, j0 = lane * 4;
    float* sX = sXall + warp * 4 * 16;
    float* sH = sHall + warp * 4 * HD;

    for (int nb = blockIdx.x; nb * 32 < NN; nb += gridDim.x) {
        int n0 = nb * 32 + warp * 4;
        stage4<16>(sX, x, n0, lane);
        __syncwarp();
        float acc[4][4];
#pragma unroll
        for (int r = 0; r < 4; ++r)
#pragma unroll
            for (int c = 0; c < 4; ++c) acc[r][c] = sb1[j0 + c];
        warp_gemm<16>(sW1, sX, j0, acc);
#pragma unroll
        for (int r = 0; r < 4; ++r) {
            float4 o;
            o.x = gelu_f(acc[r][0]); o.y = gelu_f(acc[r][1]);
            o.z = gelu_f(acc[r][2]); o.w = gelu_f(acc[r][3]);
            *(float4*)(sH + r * HD + j0) = o;
        }
        __syncwarp();
        float acc2[4][4];
#pragma unroll
        for (int r = 0; r < 4; ++r)
#pragma unroll
            for (int c = 0; c < 4; ++c) acc2[r][c] = sb2[j0 + c];
        warp_gemm<128>(sW2, sH, j0, acc2);
#pragma unroll
        for (int r = 0; r < 4; ++r) {
            int n = n0 + r;
            if (n < NN) {
                float4 o = make_float4(acc2[r][0], acc2[r][1], acc2[r][2], acc2[r][3]);
                *(float4*)(out + (size_t)n * HD + j0) = o;
            }
        }
        __syncwarp();
    }
}

// ---------------------------------------------------------------------------
// A = h @ W1_top + b1 ; B = h @ W1_bot        (W1: [256,128], top=rows 0..127)
// ---------------------------------------------------------------------------
__global__ __launch_bounds__(256, 1) void gemmAB_kernel(
    const float* __restrict__ h, const float* __restrict__ W1,
    const float* __restrict__ b1, float* __restrict__ A, float* __restrict__ B) {
    extern __shared__ float sm[];
    float* sWa = sm;                    // 128*128
    float* sWb = sWa + HD * HD;         // 128*128
    float* sb1 = sWb + HD * HD;         // 128
    float* sXall = sb1 + HD;            // 8*4*128

    for (int i = threadIdx.x; i < HD * HD / 4; i += blockDim.x) {
        ((float4*)sWa)[i] = ((const float4*)W1)[i];
        ((float4*)sWb)[i] = ((const float4*)(W1 + HD * HD))[i];
    }
    if (threadIdx.x < HD) sb1[threadIdx.x] = b1[threadIdx.x];
    __syncthreads();

    int warp = threadIdx.x >> 5, lane = threadIdx.x & 31, j0 = lane * 4;
    float* sX = sXall + warp * 4 * HD;

    for (int nb = blockIdx.x; nb * 32 < NN; nb += gridDim.x) {
        int n0 = nb * 32 + warp * 4;
        stage4<128>(sX, h, n0, lane);
        __syncwarp();
        float accA[4][4], accB[4][4];
#pragma unroll
        for (int r = 0; r < 4; ++r)
#pragma unroll
            for (int c = 0; c < 4; ++c) { accA[r][c] = sb1[j0 + c]; accB[r][c] = 0.f; }
#pragma unroll 4
        for (int k4 = 0; k4 < HD / 4; ++k4) {
            float4 xv[4];
#pragma unroll
            for (int r = 0; r < 4; ++r)
                xv[r] = *(const float4*)(sX + r * HD + k4 * 4);
#pragma unroll
            for (int kk = 0; kk < 4; ++kk) {
                int k = k4 * 4 + kk;
                float4 wa = *(const float4*)(sWa + k * HD + j0);
                float4 wb = *(const float4*)(sWb + k * HD + j0);
#pragma unroll
                for (int r = 0; r < 4; ++r) {
                    float xx = ((const float*)&xv[r])[kk];
                    accA[r][0] += xx * wa.x; accA[r][1] += xx * wa.y;
                    accA[r][2] += xx * wa.z; accA[r][3] += xx * wa.w;
                    accB[r][0] += xx * wb.x; accB[r][1] += xx * wb.y;
                    accB[r][2] += xx * wb.z; accB[r][3] += xx * wb.w;
                }
            }
        }
#pragma unroll
        for (int r = 0; r < 4; ++r) {
            int n = n0 + r;
            if (n < NN) {
                __stcg((float4*)(A + (size_t)n * HD + j0),
                       make_float4(accA[r][0], accA[r][1], accA[r][2], accA[r][3]));
                __stcg((float4*)(B + (size_t)n * HD + j0),
                       make_float4(accB[r][0], accB[r][1], accB[r][2], accB[r][3]));
            }
        }
        __syncwarp();
    }
}

// ---------------------------------------------------------------------------
// edge pass: G[dst] += gelu(A[src] + B[dst])
// one warp per edge, float4 per lane, single red.global.add.v4.f32 per lane
// ---------------------------------------------------------------------------
__global__ __launch_bounds__(256) void edge_kernel(
    const int* __restrict__ src, const int* __restrict__ dst,
    const float* __restrict__ A, const float* __restrict__ B,
    float* __restrict__ G) {
    int t = blockIdx.x * blockDim.x + threadIdx.x;
    int lane = t & 31;
    int c = lane * 4;
    int estride = (gridDim.x * blockDim.x) >> 5;
    for (int e = t >> 5; e < NE; e += estride) {
        int s = __ldg(&src[e]);
        int d = __ldg(&dst[e]);
        float4 a = __ldcg((const float4*)(A + (size_t)s * HD + c));
        float4 b = __ldcg((const float4*)(B + (size_t)d * HD + c));
        red_add_v4(G + (size_t)d * HD + c,
                   gelu_f(a.x + b.x), gelu_f(a.y + b.y),
                   gelu_f(a.z + b.z), gelu_f(a.w + b.w));
    }
}

// ---------------------------------------------------------------------------
// agg = G @ W2 + deg (.) b2
// ---------------------------------------------------------------------------
__global__ __launch_bounds__(256, 2) void agg_kernel(
    const float* __restrict__ G, const float* __restrict__ deg,
    const float* __restrict__ W2, const float* __restrict__ b2,
    float* __restrict__ out) {
    extern __shared__ float sm[];
    float* sW = sm;                 // 128*128
    float* sb2 = sW + HD * HD;      // 128
    float* sXall = sb2 + HD;        // 8*4*128
    for (int i = threadIdx.x; i < HD * HD / 4; i += blockDim.x)
        ((float4*)sW)[i] = ((const float4*)W2)[i];
    if (threadIdx.x < HD) sb2[threadIdx.x] = b2[threadIdx.x];
    __syncthreads();

    int warp = threadIdx.x >> 5, lane = threadIdx.x & 31, j0 = lane * 4;
    float* sX = sXall + warp * 4 * HD;
    for (int nb = blockIdx.x; nb * 32 < NN; nb += gridDim.x) {
        int n0 = nb * 32 + warp * 4;
        stage4<128>(sX, G, n0, lane);
        __syncwarp();
        float acc[4][4] = {};
        warp_gemm<128>(sW, sX, j0, acc);
#pragma unroll
        for (int r = 0; r < 4; ++r) {
            int n = n0 + r;
            if (n < NN) {
                float dg = deg[n];
                float4 o = make_float4(acc[r][0] + dg * sb2[j0 + 0],
                                       acc[r][1] + dg * sb2[j0 + 1],
                                       acc[r][2] + dg * sb2[j0 + 2],
                                       acc[r][3] + dg * sb2[j0 + 3]);
                *(float4*)(out + (size_t)n * HD + j0) = o;
            }
        }
        __syncwarp();
    }
}

// ---------------------------------------------------------------------------
// c1 = gelu(concat(h, agg) @ nW1 + nb1)        (nW1: [256,128])
// ---------------------------------------------------------------------------
__global__ __launch_bounds__(256, 1) void nodehid_kernel(
    const float* __restrict__ h, const float* __restrict__ agg,
    const float* __restrict__ W1, const float* __restrict__ b1,
    float* __restrict__ out) {
    extern __shared__ float sm[];
    float* sW = sm;                 // 256*128
    float* sb1 = sW + 256 * HD;     // 128
    float* sXall = sb1 + HD;        // 8*4*256
    for (int i = threadIdx.x; i < 256 * HD / 4; i += blockDim.x)
        ((float4*)sW)[i] = ((const float4*)W1)[i];
    if (threadIdx.x < HD) sb1[threadIdx.x] = b1[threadIdx.x];
    __syncthreads();

    int warp = threadIdx.x >> 5, lane = threadIdx.x & 31, j0 = lane * 4;
    float* sX = sXall + warp * 4 * 256;
    for (int nb = blockIdx.x; nb * 32 < NN; nb += gridDim.x) {
        int n0 = nb * 32 + warp * 4;
        // stage concat rows: [h | agg]
#pragma unroll
        for (int r = 0; r < 4; ++r) {
            int n = n0 + r;
            int c = lane * 4;
            float4 vh = (n < NN) ? *(const float4*)(h + (size_t)n * HD + c)
                                 : make_float4(0.f, 0.f, 0.f, 0.f);
            float4 va = (n < NN) ? *(const float4*)(agg + (size_t)n * HD + c)
                                 : make_float4(0.f, 0.f, 0.f, 0.f);
            *(float4*)(sX + r * 256 + c) = vh;
            *(float4*)(sX + r * 256 + 128 + c) = va;
        }
        __syncwarp();
        float acc[4][4];
#pragma unroll
        for (int r = 0; r < 4; ++r)
#pragma unroll
            for (int c = 0; c < 4; ++c) acc[r][c] = sb1[j0 + c];
        warp_gemm<256>(sW, sX, j0, acc);
#pragma unroll
        for (int r = 0; r < 4; ++r) {
            int n = n0 + r;
            if (n < NN) {
                float4 o = make_float4(gelu_f(acc[r][0]), gelu_f(acc[r][1]),
                                       gelu_f(acc[r][2]), gelu_f(acc[r][3]));
                *(float4*)(out + (size_t)n * HD + j0) = o;
            }
        }
        __syncwarp();
    }
}

// ---------------------------------------------------------------------------
// h += c1 @ nW2 + nb2
// ---------------------------------------------------------------------------
__global__ __launch_bounds__(256, 2) void nodeout_kernel(
    const float* __restrict__ c1, const float* __restrict__ W2,
    const float* __restrict__ b2, float* __restrict__ h) {
    extern __shared__ float sm[];
    float* sW = sm;
    float* sb2 = sW + HD * HD;
    float* sXall = sb2 + HD;
    for (int i = threadIdx.x; i < HD * HD / 4; i += blockDim.x)
        ((float4*)sW)[i] = ((const float4*)W2)[i];
    if (threadIdx.x < HD) sb2[threadIdx.x] = b2[threadIdx.x];
    __syncthreads();

    int warp = threadIdx.x >> 5, lane = threadIdx.x & 31, j0 = lane * 4;
    float* sX = sXall + warp * 4 * HD;
    for (int nb = blockIdx.x; nb * 32 < NN; nb += gridDim.x) {
        int n0 = nb * 32 + warp * 4;
        stage4<128>(sX, c1, n0, lane);
        __syncwarp();
        float acc[4][4];
#pragma unroll
        for (int r = 0; r < 4; ++r)
#pragma unroll
            for (int c = 0; c < 4; ++c) acc[r][c] = sb2[j0 + c];
        warp_gemm<128>(sW, sX, j0, acc);
#pragma unroll
        for (int r = 0; r < 4; ++r) {
            int n = n0 + r;
            if (n < NN) {
                float4 hv = *(float4*)(h + (size_t)n * HD + j0);
                hv.x += acc[r][0]; hv.y += acc[r][1];
                hv.z += acc[r][2]; hv.w += acc[r][3];
                *(float4*)(h + (size_t)n * HD + j0) = hv;
            }
        }
        __syncwarp();
    }
}

// ---------------------------------------------------------------------------
// decoder: out = gelu(h @ W1 + b1) @ W2 + b2   (W2: [128,8])
// ---------------------------------------------------------------------------
__global__ __launch_bounds__(256, 2) void decode_kernel(
    const float* __restrict__ h, const float* __restrict__ W1,
    const float* __restrict__ b1, const float* __restrict__ W2,
    const float* __restrict__ b2, float* __restrict__ out) {
    extern __shared__ float sm[];
    float* sW1 = sm;                    // 128*128
    float* sb1 = sW1 + HD * HD;         // 128
    float* sW2 = sb1 + HD;              // 128*8
    float* sb2 = sW2 + HD * 8;          // 8
    float* sXall = sb2 + 8;             // 8*4*128
    float* sHall = sXall + 8 * 4 * HD;  // 8*4*128

    for (int i = threadIdx.x; i < HD * HD / 4; i += blockDim.x)
        ((float4*)sW1)[i] = ((const float4*)W1)[i];
    for (int i = threadIdx.x; i < HD * 8 / 4; i += blockDim.x)
        ((float4*)sW2)[i] = ((const float4*)W2)[i];
    if (threadIdx.x < HD) sb1[threadIdx.x] = b1[threadIdx.x];
    if (threadIdx.x < 8) sb2[threadIdx.x] = b2[threadIdx.x];
    __syncthreads();

    int warp = threadIdx.x >> 5, lane = threadIdx.x & 31, j0 = lane * 4;
    float* sX = sXall + warp * 4 * HD;
    float* sH = sHall + warp * 4 * HD;

    for (int nb = blockIdx.x; nb * 32 < NN; nb += gridDim.x) {
        int n0 = nb * 32 + warp * 4;
        stage4<128>(sX, h, n0, lane);
        __syncwarp();
        float acc[4][4];
#pragma unroll
        for (int r = 0; r < 4; ++r)
#pragma unroll
            for (int c = 0; c < 4; ++c) acc[r][c] = sb1[j0 + c];
        warp_gemm<128>(sW1, sX, j0, acc);
#pragma unroll
        for (int r = 0; r < 4; ++r) {
            float4 o = make_float4(gelu_f(acc[r][0]), gelu_f(acc[r][1]),
                                   gelu_f(acc[r][2]), gelu_f(acc[r][3]));
            *(float4*)(sH + r * HD + j0) = o;
        }
        __syncwarp();
        // second layer: 4 rows x 8 outputs = 32 lanes, one (row, out) per lane
        int r = lane >> 3, o = lane & 7;
        float s = sb2[o];
#pragma unroll 8
        for (int k = 0; k < HD; ++k)
            s += sH[r * HD + k] * sW2[k * 8 + o];
        int n = n0 + r;
        if (n < NN) out[(size_t)n * 8 + o] = s;
        __syncwarp();
    }
}

// ---------------------------------------------------------------------------
// host launcher
// ---------------------------------------------------------------------------
extern "C" void kernel_launch(void* const* d_in, const int* in_sizes, int n_in,
                              void* d_out, int out_size) {
    const float* x     = (const float*)d_in[0];
    const int*   ei    = (const int*)d_in[1];   // [2, E] int32: src rows then dst rows
    const float* encW1 = (const float*)d_in[2];
    const float* encb1 = (const float*)d_in[3];
    const float* encW2 = (const float*)d_in[4];
    const float* encb2 = (const float*)d_in[5];
    const float* eW1   = (const float*)d_in[6];
    const float* eb1   = (const float*)d_in[7];
    const float* eW2   = (const float*)d_in[8];
    const float* eb2   = (const float*)d_in[9];
    const float* nW1   = (const float*)d_in[10];
    const float* nb1   = (const float*)d_in[11];
    const float* nW2   = (const float*)d_in[12];
    const float* nb2   = (const float*)d_in[13];
    const float* dW1   = (const float*)d_in[14];
    const float* db1   = (const float*)d_in[15];
    const float* dW2   = (const float*)d_in[16];
    const float* db2   = (const float*)d_in[17];
    float* out = (float*)d_out;

    float *p_h, *p_A, *p_B, *p_G, *p_agg, *p_tmp, *p_deg;
    cudaGetSymbolAddress((void**)&p_h, g_h);
    cudaGetSymbolAddress((void**)&p_A, g_A);
    cudaGetSymbolAddress((void**)&p_B, g_B);
    cudaGetSymbolAddress((void**)&p_G, g_G);
    cudaGetSymbolAddress((void**)&p_agg, g_agg);
    cudaGetSymbolAddress((void**)&p_tmp, g_tmp);
    cudaGetSymbolAddress((void**)&p_deg, g_deg);

    const int SM_ENC = (16 * HD + HD * HD + HD + HD + 8 * 4 * 16 + 8 * 4 * HD) * 4;
    const int SM_AB  = (2 * HD * HD + HD + 8 * 4 * HD) * 4;
    const int SM_AGG = (HD * HD + HD + 8 * 4 * HD) * 4;
    const int SM_NH  = (256 * HD + HD + 8 * 4 * 256) * 4;
    const int SM_NO  = (HD * HD + HD + 8 * 4 * HD) * 4;
    const int SM_DEC = (HD * HD + HD + HD * 8 + 8 + 2 * 8 * 4 * HD) * 4;

    cudaFuncSetAttribute(encode_kernel, cudaFuncAttributeMaxDynamicSharedMemorySize, SM_ENC);
    cudaFuncSetAttribute(gemmAB_kernel, cudaFuncAttributeMaxDynamicSharedMemorySize, SM_AB);
    cudaFuncSetAttribute(agg_kernel, cudaFuncAttributeMaxDynamicSharedMemorySize, SM_AGG);
    cudaFuncSetAttribute(nodehid_kernel, cudaFuncAttributeMaxDynamicSharedMemorySize, SM_NH);
    cudaFuncSetAttribute(nodeout_kernel, cudaFuncAttributeMaxDynamicSharedMemorySize, SM_NO);
    cudaFuncSetAttribute(decode_kernel, cudaFuncAttributeMaxDynamicSharedMemorySize, SM_DEC);

    // degrees (edge_index is launch-invariant input; recomputed deterministically)
    zero_kernel<<<(NN + 255) / 256, 256>>>(p_deg, NN);
    deg_kernel<<<(NE + 255) / 256, 256>>>(ei + NE, p_deg);

    encode_kernel<<<304, 256, SM_ENC>>>(x, encW1, encb1, encW2, encb2, p_h);

    for (int l = 0; l < NL; ++l) {
        gemmAB_kernel<<<152, 256, SM_AB>>>(p_h, eW1 + (size_t)l * 256 * HD,
                                           eb1 + l * HD, p_A, p_B);
        zero4_kernel<<<(NN * HD / 4 + 255) / 256, 256>>>((float4*)p_G, NN * HD / 4);
        edge_kernel<<<4736, 256>>>(ei, ei + NE, p_A, p_B, p_G);
        agg_kernel<<<304, 256, SM_AGG>>>(p_G, p_deg, eW2 + (size_t)l * HD * HD,
                                         eb2 + l * HD, p_agg);
        nodehid_kernel<<<152, 256, SM_NH>>>(p_h, p_agg, nW1 + (size_t)l * 256 * HD,
                                            nb1 + l * HD, p_tmp);
        nodeout_kernel<<<304, 256, SM_NO>>>(p_tmp, nW2 + (size_t)l * HD * HD,
                                            nb2 + l * HD, p_h);
    }

    decode_kernel<<<304, 256, SM_DEC>>>(p_h, dW1, db1, dW2, db2, out);
}

// round 6
// speedup vs baseline: 1.1060x; 1.1060x over previous
#include <cuda_runtime.h>
#include <math.h>

#define NN 50000
#define NE 800000
#define HD 128
#define NL 4

// scratch (allocation-free rule: __device__ globals)
__device__ float g_h[NN * HD];
__device__ float g_A[NN * HD];
__device__ float g_B[NN * HD];
__device__ float g_G[NN * HD];
__device__ float g_tmp[NN * HD];
__device__ float g_M[HD * HD];
__device__ float g_v[HD];
__device__ int   g_rowptr[NN + 1];
__device__ int   g_cnt[NN];
__device__ int   g_adj[NE];

__device__ __forceinline__ float gelu_f(float x) {
    return 0.5f * x * (1.0f + erff(x * 0.70710678118654752440f));
}

// ---- f32x2 packed-FMA helpers (exact fp32 semantics, FFMA2 in SASS) ----
__device__ __forceinline__ unsigned long long pack2(float lo, float hi) {
    unsigned long long r;
    asm("mov.b64 %0, {%1, %2};" : "=l"(r) : "f"(lo), "f"(hi));
    return r;
}
__device__ __forceinline__ void unpack2(unsigned long long v, float& lo, float& hi) {
    asm("mov.b64 {%0, %1}, %2;" : "=f"(lo), "=f"(hi) : "l"(v));
}
__device__ __forceinline__ void ffma2(unsigned long long& d,
                                      unsigned long long a, unsigned long long b) {
    asm("fma.rn.f32x2 %0, %1, %2, %0;" : "+l"(d) : "l"(a), "l"(b));
}

// ---------------------------------------------------------------------------
// Warp-cooperative packed GEMM tile: each warp computes 4 nodes x 128 outputs.
// accp[r][0] = cols (j0, j0+1), accp[r][1] = cols (j0+2, j0+3), packed f32x2.
// sW rows are 16B-aligned at j0, so weight pairs load directly as ulonglong2.
// ---------------------------------------------------------------------------
template <int K>
__device__ __forceinline__ void warp_gemm2(const float* __restrict__ sW,
                                           const float* __restrict__ sX,
                                           int j0, unsigned long long accp[4][2]) {
#pragma unroll 4
    for (int k4 = 0; k4 < K / 4; ++k4) {
        float4 xv[4];
#pragma unroll
        for (int r = 0; r < 4; ++r)
            xv[r] = *(const float4*)(sX + r * K + k4 * 4);
#pragma unroll
        for (int kk = 0; kk < 4; ++kk) {
            ulonglong2 wv = *(const ulonglong2*)(sW + (k4 * 4 + kk) * HD + j0);
#pragma unroll
            for (int r = 0; r < 4; ++r) {
                float x = ((const float*)&xv[r])[kk];
                unsigned long long xp = pack2(x, x);
                ffma2(accp[r][0], xp, wv.x);
                ffma2(accp[r][1], xp, wv.y);
            }
        }
    }
}

template <int K>
__device__ __forceinline__ void stage4(float* sX, const float* __restrict__ gX,
                                       int n0, int lane) {
#pragma unroll
    for (int r = 0; r < 4; ++r) {
        int n = n0 + r;
#pragma unroll
        for (int c0 = 0; c0 < K; c0 += 128) {
            int c = c0 + lane * 4;
            if (c < K) {
                float4 v = (n < NN) ? *(const float4*)(gX + (size_t)n * K + c)
                                    : make_float4(0.f, 0.f, 0.f, 0.f);
                *(float4*)(sX + r * K + c) = v;
            }
        }
    }
}

// ---------------------------------------------------------------------------
// CSR build kernels
// ---------------------------------------------------------------------------
__global__ void zero_int_kernel(int* p, int n) {
    int i = blockIdx.x * blockDim.x + threadIdx.x;
    if (i < n) p[i] = 0;
}
__global__ void count_kernel(const int* __restrict__ dst, int* cnt) {
    int e = blockIdx.x * blockDim.x + threadIdx.x;
    if (e < NE) atomicAdd(&cnt[dst[e]], 1);
}
__global__ void scan_kernel(const int* __restrict__ cnt, int* rowptr) {
    __shared__ int ssum[1024];
    int t = threadIdx.x;
    const int CH = (NN + 1023) / 1024;
    int b0 = t * CH;
    int s = 0;
    for (int i = 0; i < CH; ++i)
        if (b0 + i < NN) s += cnt[b0 + i];
    ssum[t] = s;
    __syncthreads();
    for (int off = 1; off < 1024; off <<= 1) {
        int v = (t >= off) ? ssum[t - off] : 0;
        __syncthreads();
        ssum[t] += v;
        __syncthreads();
    }
    int run = (t > 0) ? ssum[t - 1] : 0;
    for (int i = 0; i < CH; ++i) {
        if (b0 + i < NN) {
            rowptr[b0 + i] = run;
            run += cnt[b0 + i];
        }
    }
    if (t == 1023) rowptr[NN] = run;
}
__global__ void fill_kernel(const int* __restrict__ src, const int* __restrict__ dst,
                            const int* __restrict__ rowptr, int* cur, int* adj) {
    int e = blockIdx.x * blockDim.x + threadIdx.x;
    if (e < NE) {
        int d = dst[e];
        int pos = atomicAdd(&cur[d], 1);
        adj[rowptr[d] + pos] = src[e];
    }
}

// ---------------------------------------------------------------------------
// encoder: h = gelu(x @ W1 + b1) @ W2 + b2      (x: [N,16])
// ---------------------------------------------------------------------------
__global__ __launch_bounds__(256, 2) void encode_kernel(
    const float* __restrict__ x, const float* __restrict__ W1,
    const float* __restrict__ b1, const float* __restrict__ W2,
    const float* __restrict__ b2, float* __restrict__ out) {
    extern __shared__ float sm[];
    float* sW1 = sm;                      // 16*128
    float* sW2 = sW1 + 16 * HD;           // 128*128
    float* sb1 = sW2 + HD * HD;
    float* sb2 = sb1 + HD;
    float* sXall = sb2 + HD;              // 8*4*16
    float* sHall = sXall + 8 * 4 * 16;    // 8*4*128

    for (int i = threadIdx.x; i < 16 * HD / 4; i += blockDim.x)
        ((float4*)sW1)[i] = ((const float4*)W1)[i];
    for (int i = threadIdx.x; i < HD * HD / 4; i += blockDim.x)
        ((float4*)sW2)[i] = ((const float4*)W2)[i];
    if (threadIdx.x < HD) {
        sb1[threadIdx.x] = b1[threadIdx.x];
        sb2[threadIdx.x] = b2[threadIdx.x];
    }
    __syncthreads();

    int warp = threadIdx.x >> 5, lane = threadIdx.x & 31, j0 = lane * 4;
    float* sX = sXall + warp * 4 * 16;
    float* sH = sHall + warp * 4 * HD;

    unsigned long long bp1_0 = pack2(sb1[j0], sb1[j0 + 1]);
    unsigned long long bp1_1 = pack2(sb1[j0 + 2], sb1[j0 + 3]);
    unsigned long long bp2_0 = pack2(sb2[j0], sb2[j0 + 1]);
    unsigned long long bp2_1 = pack2(sb2[j0 + 2], sb2[j0 + 3]);

    for (int nb = blockIdx.x; nb * 32 < NN; nb += gridDim.x) {
        int n0 = nb * 32 + warp * 4;
        stage4<16>(sX, x, n0, lane);
        __syncwarp();
        unsigned long long accp[4][2];
#pragma unroll
        for (int r = 0; r < 4; ++r) { accp[r][0] = bp1_0; accp[r][1] = bp1_1; }
        warp_gemm2<16>(sW1, sX, j0, accp);
#pragma unroll
        for (int r = 0; r < 4; ++r) {
            float a0, a1, a2, a3;
            unpack2(accp[r][0], a0, a1);
            unpack2(accp[r][1], a2, a3);
            float4 o;
            o.x = gelu_f(a0); o.y = gelu_f(a1);
            o.z = gelu_f(a2); o.w = gelu_f(a3);
            *(float4*)(sH + r * HD + j0) = o;
        }
        __syncwarp();
        unsigned long long acc2[4][2];
#pragma unroll
        for (int r = 0; r < 4; ++r) { acc2[r][0] = bp2_0; acc2[r][1] = bp2_1; }
        warp_gemm2<128>(sW2, sH, j0, acc2);
#pragma unroll
        for (int r = 0; r < 4; ++r) {
            int n = n0 + r;
            if (n < NN) {
                float4 o;
                unpack2(acc2[r][0], o.x, o.y);
                unpack2(acc2[r][1], o.z, o.w);
                *(float4*)(out + (size_t)n * HD + j0) = o;
            }
        }
        __syncwarp();
    }
}

// ---------------------------------------------------------------------------
// A = h @ W1_top + b1 ; B = h @ W1_bot        (W1: [256,128])
// ---------------------------------------------------------------------------
__global__ __launch_bounds__(256, 1) void gemmAB_kernel(
    const float* __restrict__ h, const float* __restrict__ W1,
    const float* __restrict__ b1, float* __restrict__ A, float* __restrict__ B) {
    extern __shared__ float sm[];
    float* sWa = sm;                    // 128*128
    float* sWb = sWa + HD * HD;         // 128*128
    float* sb1 = sWb + HD * HD;
    float* sXall = sb1 + HD;            // 8*4*128

    for (int i = threadIdx.x; i < HD * HD / 4; i += blockDim.x) {
        ((float4*)sWa)[i] = ((const float4*)W1)[i];
        ((float4*)sWb)[i] = ((const float4*)(W1 + HD * HD))[i];
    }
    if (threadIdx.x < HD) sb1[threadIdx.x] = b1[threadIdx.x];
    __syncthreads();

    int warp = threadIdx.x >> 5, lane = threadIdx.x & 31, j0 = lane * 4;
    float* sX = sXall + warp * 4 * HD;

    unsigned long long bp0 = pack2(sb1[j0], sb1[j0 + 1]);
    unsigned long long bp1 = pack2(sb1[j0 + 2], sb1[j0 + 3]);

    for (int nb = blockIdx.x; nb * 32 < NN; nb += gridDim.x) {
        int n0 = nb * 32 + warp * 4;
        stage4<128>(sX, h, n0, lane);
        __syncwarp();
        unsigned long long accA[4][2], accB[4][2];
        const unsigned long long z = pack2(0.f, 0.f);
#pragma unroll
        for (int r = 0; r < 4; ++r) {
            accA[r][0] = bp0; accA[r][1] = bp1;
            accB[r][0] = z;   accB[r][1] = z;
        }
#pragma unroll 4
        for (int k4 = 0; k4 < HD / 4; ++k4) {
            float4 xv[4];
#pragma unroll
            for (int r = 0; r < 4; ++r)
                xv[r] = *(const float4*)(sX + r * HD + k4 * 4);
#pragma unroll
            for (int kk = 0; kk < 4; ++kk) {
                int k = k4 * 4 + kk;
                ulonglong2 wa = *(const ulonglong2*)(sWa + k * HD + j0);
                ulonglong2 wb = *(const ulonglong2*)(sWb + k * HD + j0);
#pragma unroll
                for (int r = 0; r < 4; ++r) {
                    float xx = ((const float*)&xv[r])[kk];
                    unsigned long long xp = pack2(xx, xx);
                    ffma2(accA[r][0], xp, wa.x);
                    ffma2(accA[r][1], xp, wa.y);
                    ffma2(accB[r][0], xp, wb.x);
                    ffma2(accB[r][1], xp, wb.y);
                }
            }
        }
#pragma unroll
        for (int r = 0; r < 4; ++r) {
            int n = n0 + r;
            if (n < NN) {
                float4 oa, ob;
                unpack2(accA[r][0], oa.x, oa.y);
                unpack2(accA[r][1], oa.z, oa.w);
                unpack2(accB[r][0], ob.x, ob.y);
                unpack2(accB[r][1], ob.z, ob.w);
                __stcg((float4*)(A + (size_t)n * HD + j0), oa);
                __stcg((float4*)(B + (size_t)n * HD + j0), ob);
            }
        }
        __syncwarp();
    }
}

// ---------------------------------------------------------------------------
// CSR edge pass: G[n] = sum_{s in adj[row n]} gelu(A[s] + B[n])
// one warp per dst node, float4 per lane; no atomics.
// ---------------------------------------------------------------------------
__global__ __launch_bounds__(256) void edge_csr_kernel(
    const int* __restrict__ rowptr, const int* __restrict__ adj,
    const float* __restrict__ A, const float* __restrict__ B,
    float* __restrict__ G) {
    int t = blockIdx.x * blockDim.x + threadIdx.x;
    int lane = t & 31;
    int c = lane * 4;
    int nwarps = (gridDim.x * blockDim.x) >> 5;
    for (int n = t >> 5; n < NN; n += nwarps) {
        int beg = __ldg(&rowptr[n]), end = __ldg(&rowptr[n + 1]);
        float4 b = __ldg((const float4*)(B + (size_t)n * HD + c));
        float4 g = make_float4(0.f, 0.f, 0.f, 0.f);
        for (int i = beg; i < end; i += 32) {
            int m = min(32, end - i);
            int s = (i + lane < end) ? __ldg(&adj[i + lane]) : 0;
#pragma unroll 8
            for (int k = 0; k < m; ++k) {
                int sk = __shfl_sync(0xffffffff, s, k);
                float4 a = *(const float4*)(A + (size_t)sk * HD + c);
                g.x += gelu_f(a.x + b.x);
                g.y += gelu_f(a.y + b.y);
                g.z += gelu_f(a.z + b.z);
                g.w += gelu_f(a.w + b.w);
            }
        }
        __stcg((float4*)(G + (size_t)n * HD + c), g);
    }
}

// ---------------------------------------------------------------------------
// per-layer weight fold: M = eW2 @ nW1_bot, v = eb2 @ nW1_bot
// ---------------------------------------------------------------------------
__global__ void prepM_kernel(const float* __restrict__ eW2,
                             const float* __restrict__ eb2,
                             const float* __restrict__ nW1,
                             float* __restrict__ M, float* __restrict__ v) {
    int idx = blockIdx.x * blockDim.x + threadIdx.x;   // 64 blocks x 256
    int i = idx >> 7, j = idx & 127;
    float s = 0.f;
#pragma unroll 8
    for (int k = 0; k < HD; ++k)
        s += eW2[i * HD + k] * nW1[(size_t)(HD + k) * HD + j];
    M[idx] = s;
    if (i == 0) {
        float sv = 0.f;
#pragma unroll 8
        for (int k = 0; k < HD; ++k)
            sv += eb2[k] * nW1[(size_t)(HD + k) * HD + j];
        v[j] = sv;
    }
}

// ---------------------------------------------------------------------------
// fused node-hidden: c1 = gelu(h @ nW1_top + G @ M + deg*v + nb1)
// ---------------------------------------------------------------------------
__global__ __launch_bounds__(256, 1) void nodehid_kernel(
    const float* __restrict__ h, const float* __restrict__ G,
    const int* __restrict__ rowptr,
    const float* __restrict__ W1, const float* __restrict__ M,
    const float* __restrict__ v, const float* __restrict__ b1,
    float* __restrict__ out) {
    extern __shared__ float sm[];
    float* sWa = sm;                    // 128*128 (nW1 top)
    float* sWb = sWa + HD * HD;         // 128*128 (M)
    float* sb1 = sWb + HD * HD;
    float* sv  = sb1 + HD;
    float* sXall = sv + HD;             // 8*4*128
    float* sGall = sXall + 8 * 4 * HD;  // 8*4*128

    for (int i = threadIdx.x; i < HD * HD / 4; i += blockDim.x) {
        ((float4*)sWa)[i] = ((const float4*)W1)[i];
        ((float4*)sWb)[i] = ((const float4*)M)[i];
    }
    if (threadIdx.x < HD) {
        sb1[threadIdx.x] = b1[threadIdx.x];
        sv[threadIdx.x] = v[threadIdx.x];
    }
    __syncthreads();

    int warp = threadIdx.x >> 5, lane = threadIdx.x & 31, j0 = lane * 4;
    float* sX = sXall + warp * 4 * HD;
    float* sG = sGall + warp * 4 * HD;

    for (int nb = blockIdx.x; nb * 32 < NN; nb += gridDim.x) {
        int n0 = nb * 32 + warp * 4;
        stage4<128>(sX, h, n0, lane);
        stage4<128>(sG, G, n0, lane);
        __syncwarp();
        unsigned long long accp[4][2];
#pragma unroll
        for (int r = 0; r < 4; ++r) {
            int n = n0 + r;
            float dg = (n < NN) ? (float)(__ldg(&rowptr[n + 1]) - __ldg(&rowptr[n])) : 0.f;
            accp[r][0] = pack2(sb1[j0 + 0] + dg * sv[j0 + 0],
                               sb1[j0 + 1] + dg * sv[j0 + 1]);
            accp[r][1] = pack2(sb1[j0 + 2] + dg * sv[j0 + 2],
                               sb1[j0 + 3] + dg * sv[j0 + 3]);
        }
#pragma unroll 4
        for (int k4 = 0; k4 < HD / 4; ++k4) {
            float4 xv[4], gv[4];
#pragma unroll
            for (int r = 0; r < 4; ++r) {
                xv[r] = *(const float4*)(sX + r * HD + k4 * 4);
                gv[r] = *(const float4*)(sG + r * HD + k4 * 4);
            }
#pragma unroll
            for (int kk = 0; kk < 4; ++kk) {
                int k = k4 * 4 + kk;
                ulonglong2 wa = *(const ulonglong2*)(sWa + k * HD + j0);
                ulonglong2 wb = *(const ulonglong2*)(sWb + k * HD + j0);
#pragma unroll
                for (int r = 0; r < 4; ++r) {
                    float xx = ((const float*)&xv[r])[kk];
                    float gg = ((const float*)&gv[r])[kk];
                    unsigned long long xp = pack2(xx, xx);
                    unsigned long long gp = pack2(gg, gg);
                    ffma2(accp[r][0], xp, wa.x);
                    ffma2(accp[r][1], xp, wa.y);
                    ffma2(accp[r][0], gp, wb.x);
                    ffma2(accp[r][1], gp, wb.y);
                }
            }
        }
#pragma unroll
        for (int r = 0; r < 4; ++r) {
            int n = n0 + r;
            if (n < NN) {
                float a0, a1, a2, a3;
                unpack2(accp[r][0], a0, a1);
                unpack2(accp[r][1], a2, a3);
                float4 o = make_float4(gelu_f(a0), gelu_f(a1), gelu_f(a2), gelu_f(a3));
                *(float4*)(out + (size_t)n * HD + j0) = o;
            }
        }
        __syncwarp();
    }
}

// ---------------------------------------------------------------------------
// h += c1 @ nW2 + nb2
// ---------------------------------------------------------------------------
__global__ __launch_bounds__(256, 2) void nodeout_kernel(
    const float* __restrict__ c1, const float* __restrict__ W2,
    const float* __restrict__ b2, float* __restrict__ h) {
    extern __shared__ float sm[];
    float* sW = sm;
    float* sb2 = sW + HD * HD;
    float* sXall = sb2 + HD;
    for (int i = threadIdx.x; i < HD * HD / 4; i += blockDim.x)
        ((float4*)sW)[i] = ((const float4*)W2)[i];
    if (threadIdx.x < HD) sb2[threadIdx.x] = b2[threadIdx.x];
    __syncthreads();

    int warp = threadIdx.x >> 5, lane = threadIdx.x & 31, j0 = lane * 4;
    float* sX = sXall + warp * 4 * HD;
    unsigned long long bp0 = pack2(sb2[j0], sb2[j0 + 1]);
    unsigned long long bp1 = pack2(sb2[j0 + 2], sb2[j0 + 3]);

    for (int nb = blockIdx.x; nb * 32 < NN; nb += gridDim.x) {
        int n0 = nb * 32 + warp * 4;
        stage4<128>(sX, c1, n0, lane);
        __syncwarp();
        unsigned long long accp[4][2];
#pragma unroll
        for (int r = 0; r < 4; ++r) { accp[r][0] = bp0; accp[r][1] = bp1; }
        warp_gemm2<128>(sW, sX, j0, accp);
#pragma unroll
        for (int r = 0; r < 4; ++r) {
            int n = n0 + r;
            if (n < NN) {
                float a0, a1, a2, a3;
                unpack2(accp[r][0], a0, a1);
                unpack2(accp[r][1], a2, a3);
                float4 hv = *(float4*)(h + (size_t)n * HD + j0);
                hv.x += a0; hv.y += a1; hv.z += a2; hv.w += a3;
                *(float4*)(h + (size_t)n * HD + j0) = hv;
            }
        }
        __syncwarp();
    }
}

// ---------------------------------------------------------------------------
// decoder: out = gelu(h @ W1 + b1) @ W2 + b2   (W2: [128,8])
// ---------------------------------------------------------------------------
__global__ __launch_bounds__(256, 2) void decode_kernel(
    const float* __restrict__ h, const float* __restrict__ W1,
    const float* __restrict__ b1, const float* __restrict__ W2,
    const float* __restrict__ b2, float* __restrict__ out) {
    extern __shared__ float sm[];
    float* sW1 = sm;                    // 128*128
    float* sb1 = sW1 + HD * HD;
    float* sW2 = sb1 + HD;              // 128*8
    float* sb2 = sW2 + HD * 8;
    float* sXall = sb2 + 8;             // 8*4*128
    float* sHall = sXall + 8 * 4 * HD;  // 8*4*128

    for (int i = threadIdx.x; i < HD * HD / 4; i += blockDim.x)
        ((float4*)sW1)[i] = ((const float4*)W1)[i];
    for (int i = threadIdx.x; i < HD * 8 / 4; i += blockDim.x)
        ((float4*)sW2)[i] = ((const float4*)W2)[i];
    if (threadIdx.x < HD) sb1[threadIdx.x] = b1[threadIdx.x];
    if (threadIdx.x < 8) sb2[threadIdx.x] = b2[threadIdx.x];
    __syncthreads();

    int warp = threadIdx.x >> 5, lane = threadIdx.x & 31, j0 = lane * 4;
    float* sX = sXall + warp * 4 * HD;
    float* sH = sHall + warp * 4 * HD;
    unsigned long long bp0 = pack2(sb1[j0], sb1[j0 + 1]);
    unsigned long long bp1 = pack2(sb1[j0 + 2], sb1[j0 + 3]);

    for (int nb = blockIdx.x; nb * 32 < NN; nb += gridDim.x) {
        int n0 = nb * 32 + warp * 4;
        stage4<128>(sX, h, n0, lane);
        __syncwarp();
        unsigned long long accp[4][2];
#pragma unroll
        for (int r = 0; r < 4; ++r) { accp[r][0] = bp0; accp[r][1] = bp1; }
        warp_gemm2<128>(sW1, sX, j0, accp);
#pragma unroll
        for (int r = 0; r < 4; ++r) {
            float a0, a1, a2, a3;
            unpack2(accp[r][0], a0, a1);
            unpack2(accp[r][1], a2, a3);
            float4 o = make_float4(gelu_f(a0), gelu_f(a1), gelu_f(a2), gelu_f(a3));
            *(float4*)(sH + r * HD + j0) = o;
        }
        __syncwarp();
        int r = lane >> 3, o = lane & 7;
        float s = sb2[o];
#pragma unroll 8
        for (int k = 0; k < HD; ++k)
            s += sH[r * HD + k] * sW2[k * 8 + o];
        int n = n0 + r;
        if (n < NN) out[(size_t)n * 8 + o] = s;
        __syncwarp();
    }
}

// ---------------------------------------------------------------------------
// host launcher
// ---------------------------------------------------------------------------
extern "C" void kernel_launch(void* const* d_in, const int* in_sizes, int n_in,
                              void* d_out, int out_size) {
    const float* x     = (const float*)d_in[0];
    const int*   ei    = (const int*)d_in[1];   // [2, E] int32
    const float* encW1 = (const float*)d_in[2];
    const float* encb1 = (const float*)d_in[3];
    const float* encW2 = (const float*)d_in[4];
    const float* encb2 = (const float*)d_in[5];
    const float* eW1   = (const float*)d_in[6];
    const float* eb1   = (const float*)d_in[7];
    const float* eW2   = (const float*)d_in[8];
    const float* eb2   = (const float*)d_in[9];
    const float* nW1   = (const float*)d_in[10];
    const float* nb1   = (const float*)d_in[11];
    const float* nW2   = (const float*)d_in[12];
    const float* nb2   = (const float*)d_in[13];
    const float* dW1   = (const float*)d_in[14];
    const float* db1   = (const float*)d_in[15];
    const float* dW2   = (const float*)d_in[16];
    const float* db2   = (const float*)d_in[17];
    float* out = (float*)d_out;

    float *p_h, *p_A, *p_B, *p_G, *p_tmp, *p_M, *p_v;
    int *p_rowptr, *p_cnt, *p_adj;
    cudaGetSymbolAddress((void**)&p_h, g_h);
    cudaGetSymbolAddress((void**)&p_A, g_A);
    cudaGetSymbolAddress((void**)&p_B, g_B);
    cudaGetSymbolAddress((void**)&p_G, g_G);
    cudaGetSymbolAddress((void**)&p_tmp, g_tmp);
    cudaGetSymbolAddress((void**)&p_M, g_M);
    cudaGetSymbolAddress((void**)&p_v, g_v);
    cudaGetSymbolAddress((void**)&p_rowptr, g_rowptr);
    cudaGetSymbolAddress((void**)&p_cnt, g_cnt);
    cudaGetSymbolAddress((void**)&p_adj, g_adj);

    const int SM_ENC = (16 * HD + HD * HD + 2 * HD + 8 * 4 * 16 + 8 * 4 * HD) * 4;
    const int SM_AB  = (2 * HD * HD + HD + 8 * 4 * HD) * 4;
    const int SM_NH  = (2 * HD * HD + 2 * HD + 2 * 8 * 4 * HD) * 4;
    const int SM_NO  = (HD * HD + HD + 8 * 4 * HD) * 4;
    const int SM_DEC = (HD * HD + HD + HD * 8 + 8 + 2 * 8 * 4 * HD) * 4;

    cudaFuncSetAttribute(encode_kernel, cudaFuncAttributeMaxDynamicSharedMemorySize, SM_ENC);
    cudaFuncSetAttribute(gemmAB_kernel, cudaFuncAttributeMaxDynamicSharedMemorySize, SM_AB);
    cudaFuncSetAttribute(nodehid_kernel, cudaFuncAttributeMaxDynamicSharedMemorySize, SM_NH);
    cudaFuncSetAttribute(nodeout_kernel, cudaFuncAttributeMaxDynamicSharedMemorySize, SM_NO);
    cudaFuncSetAttribute(decode_kernel, cudaFuncAttributeMaxDynamicSharedMemorySize, SM_DEC);

    // ---- build dst-CSR (deterministic recompute each launch) ----
    zero_int_kernel<<<(NN + 255) / 256, 256>>>(p_cnt, NN);
    count_kernel<<<(NE + 255) / 256, 256>>>(ei + NE, p_cnt);
    scan_kernel<<<1, 1024>>>(p_cnt, p_rowptr);
    zero_int_kernel<<<(NN + 255) / 256, 256>>>(p_cnt, NN);
    fill_kernel<<<(NE + 255) / 256, 256>>>(ei, ei + NE, p_rowptr, p_cnt, p_adj);

    encode_kernel<<<304, 256, SM_ENC>>>(x, encW1, encb1, encW2, encb2, p_h);

    for (int l = 0; l < NL; ++l) {
        prepM_kernel<<<64, 256>>>(eW2 + (size_t)l * HD * HD, eb2 + l * HD,
                                  nW1 + (size_t)l * 256 * HD, p_M, p_v);
        gemmAB_kernel<<<152, 256, SM_AB>>>(p_h, eW1 + (size_t)l * 256 * HD,
                                           eb1 + l * HD, p_A, p_B);
        edge_csr_kernel<<<2368, 256>>>(p_rowptr, p_adj, p_A, p_B, p_G);
        nodehid_kernel<<<152, 256, SM_NH>>>(p_h, p_G, p_rowptr,
                                            nW1 + (size_t)l * 256 * HD, p_M, p_v,
                                            nb1 + l * HD, p_tmp);
        nodeout_kernel<<<304, 256, SM_NO>>>(p_tmp, nW2 + (size_t)l * HD * HD,
                                            nb2 + l * HD, p_h);
    }

    decode_kernel<<<304, 256, SM_DEC>>>(p_h, dW1, db1, dW2, db2, out);
}

// round 10
// speedup vs baseline: 1.2299x; 1.1120x over previous
#include <cuda_runtime.h>
#include <cuda_bf16.h>
#include <math.h>
#include <stdint.h>

#define NN 50000
#define NE 800000
#define HD 128
#define NL 4
#define TILES ((NN + 127) / 128)
#define WSTRIDE 136   // padded bf16 row stride for weight smem (conflict-free B loads)

// scratch (allocation-free rule: __device__ globals)
__device__ float g_h[NN * HD];
__device__ float g_A[NN * HD];
__device__ float g_B[NN * HD];
__device__ float g_G[NN * HD];
__device__ float g_tmp[NN * HD];
__device__ float g_M[HD * HD];
__device__ float g_v[HD];
__device__ float g_zero[HD];           // stays zero
__device__ int   g_rowptr[NN + 1];
__device__ int   g_cnt[NN];
__device__ int   g_adj[NE];

__device__ __forceinline__ float gelu_f(float x) {
    return 0.5f * x * (1.0f + erff(x * 0.70710678118654752440f));
}

// =========================== mma.sync helpers ==============================
// D = A(16x16 bf16, row) @ B(16x8 bf16, col) + D, fp32 accum.
__device__ __forceinline__ void mma_bf16(float* c, const uint32_t* a,
                                         uint32_t b0, uint32_t b1) {
    asm volatile(
        "mma.sync.aligned.m16n8k16.row.col.f32.bf16.bf16.f32 "
        "{%0,%1,%2,%3}, {%4,%5,%6,%7}, {%8,%9}, {%0,%1,%2,%3};"
        : "+f"(c[0]), "+f"(c[1]), "+f"(c[2]), "+f"(c[3])
        : "r"(a[0]), "r"(a[1]), "r"(a[2]), "r"(a[3]), "r"(b0), "r"(b1));
}

// float2 -> packed bf16x2 hi and residual-lo (low element in low 16 bits)
__device__ __forceinline__ void cvt_hi_lo(float2 x, uint32_t& hi, uint32_t& lo) {
    __nv_bfloat162 h, l;
    h.x = __float2bfloat16(x.x);
    h.y = __float2bfloat16(x.y);
    l.x = __float2bfloat16(x.x - __bfloat162float(h.x));
    l.y = __float2bfloat16(x.y - __bfloat162float(h.y));
    hi = *reinterpret_cast<uint32_t*>(&h);
    lo = *reinterpret_cast<uint32_t*>(&l);
}

// =========================== mma GEMM ======================================
// out[tiles of 128 rows, 128] = sum_p X_p @ W_p (+bias)(+deg*v) with epilogue:
//   EPI 0: store   EPI 1: gelu(store + deg*v)   EPI 2: out += result
// W: [128 in][128 out] fp32 row-major; converted in-kernel to transposed
// bf16 hi/lo smem images Wt[n][k] with row stride WSTRIDE.
template <int NPAIR, int EPI>
__global__ __launch_bounds__(256, 1) void mma_gemm_kernel(
    const float* __restrict__ X0, const float* __restrict__ W0,
    const float* __restrict__ X1, const float* __restrict__ W1,
    const float* __restrict__ bias, const float* __restrict__ v,
    const int* __restrict__ rowptr, float* __restrict__ out) {
    extern __shared__ char smraw[];
    __nv_bfloat16* sw = (__nv_bfloat16*)smraw;
    float* sbias = (float*)(smraw + (size_t)NPAIR * 2 * 128 * WSTRIDE * 2);
    float* sv = sbias + HD;
    int tid = threadIdx.x, wid = tid >> 5, lane = tid & 31;
    int g = lane >> 2, t = lane & 3;

    // ---- convert weights: transpose + hi/lo split into smem ----
    for (int p = 0; p < NPAIR; ++p) {
        const float* W = p ? W1 : W0;
        __nv_bfloat16* hi = sw + (size_t)p * 2 * 128 * WSTRIDE;
        __nv_bfloat16* lo = hi + 128 * WSTRIDE;
        for (int i = tid; i < 128 * 128; i += 256) {
            int k = i >> 7, n = i & 127;
            float w = W[i];
            __nv_bfloat16 h = __float2bfloat16(w);
            hi[n * WSTRIDE + k] = h;
            lo[n * WSTRIDE + k] = __float2bfloat16(w - __bfloat162float(h));
        }
    }
    if (tid < HD) sbias[tid] = bias[tid];
    if (EPI == 1 && tid < HD) sv[tid] = v[tid];
    __syncthreads();

    for (int tile = blockIdx.x; tile < TILES; tile += gridDim.x) {
        int rbase = tile * 128 + wid * 16;
        int r0 = rbase + g, r1 = rbase + g + 8;
        bool ok0 = r0 < NN, ok1 = r1 < NN;
        float acc[16][4];
#pragma unroll
        for (int nt = 0; nt < 16; ++nt) {
            acc[nt][0] = 0.f; acc[nt][1] = 0.f;
            acc[nt][2] = 0.f; acc[nt][3] = 0.f;
        }

#pragma unroll
        for (int p = 0; p < NPAIR; ++p) {
            const float* X = p ? X1 : X0;
            uint32_t ahi[8][4], alo[8][4];
#pragma unroll
            for (int ks = 0; ks < 8; ++ks) {
                int k0 = ks * 16 + 2 * t;
                float2 z = make_float2(0.f, 0.f);
                float2 xa0 = ok0 ? *(const float2*)(X + (size_t)r0 * HD + k0)     : z;
                float2 xa1 = ok1 ? *(const float2*)(X + (size_t)r1 * HD + k0)     : z;
                float2 xa2 = ok0 ? *(const float2*)(X + (size_t)r0 * HD + k0 + 8) : z;
                float2 xa3 = ok1 ? *(const float2*)(X + (size_t)r1 * HD + k0 + 8) : z;
                cvt_hi_lo(xa0, ahi[ks][0], alo[ks][0]);
                cvt_hi_lo(xa1, ahi[ks][1], alo[ks][1]);
                cvt_hi_lo(xa2, ahi[ks][2], alo[ks][2]);
                cvt_hi_lo(xa3, ahi[ks][3], alo[ks][3]);
            }
            const __nv_bfloat16* hi = sw + (size_t)p * 2 * 128 * WSTRIDE;
            const __nv_bfloat16* lo = hi + 128 * WSTRIDE;
#pragma unroll
            for (int ks = 0; ks < 8; ++ks) {
                int kb = ks * 16 + 2 * t;
#pragma unroll
                for (int nt = 0; nt < 16; ++nt) {
                    int n = nt * 8 + g;
                    uint32_t b0h = *(const uint32_t*)(hi + n * WSTRIDE + kb);
                    uint32_t b1h = *(const uint32_t*)(hi + n * WSTRIDE + kb + 8);
                    uint32_t b0l = *(const uint32_t*)(lo + n * WSTRIDE + kb);
                    uint32_t b1l = *(const uint32_t*)(lo + n * WSTRIDE + kb + 8);
                    mma_bf16(acc[nt], ahi[ks], b0h, b1h);
                    mma_bf16(acc[nt], ahi[ks], b0l, b1l);
                    mma_bf16(acc[nt], alo[ks], b0h, b1h);
                }
            }
        }

        // ---- epilogue ----
        float dgv0 = 0.f, dgv1 = 0.f;
        if (EPI == 1) {
            if (ok0) dgv0 = (float)(rowptr[r0 + 1] - rowptr[r0]);
            if (ok1) dgv1 = (float)(rowptr[r1 + 1] - rowptr[r1]);
        }
#pragma unroll
        for (int nt = 0; nt < 16; ++nt) {
            int c = nt * 8 + 2 * t;
            float bb0 = sbias[c], bb1 = sbias[c + 1];
            float d0 = acc[nt][0] + bb0, d1 = acc[nt][1] + bb1;
            float d2 = acc[nt][2] + bb0, d3 = acc[nt][3] + bb1;
            if (EPI == 1) {
                float vv0 = sv[c], vv1 = sv[c + 1];
                d0 = gelu_f(d0 + dgv0 * vv0); d1 = gelu_f(d1 + dgv0 * vv1);
                d2 = gelu_f(d2 + dgv1 * vv0); d3 = gelu_f(d3 + dgv1 * vv1);
            }
            if (ok0) {
                float* o = out + (size_t)r0 * HD + c;
                if (EPI == 2) { float2 hv = *(float2*)o; d0 += hv.x; d1 += hv.y; }
                *(float2*)o = make_float2(d0, d1);
            }
            if (ok1) {
                float* o = out + (size_t)r1 * HD + c;
                if (EPI == 2) { float2 hv = *(float2*)o; d2 += hv.x; d3 += hv.y; }
                *(float2*)o = make_float2(d2, d3);
            }
        }
    }
}

// =========================== fp32 helpers (enc/dec) ========================
__device__ __forceinline__ unsigned long long pack2(float lo, float hi) {
    unsigned long long r;
    asm("mov.b64 %0, {%1, %2};" : "=l"(r) : "f"(lo), "f"(hi));
    return r;
}
__device__ __forceinline__ void unpack2(unsigned long long v, float& lo, float& hi) {
    asm("mov.b64 {%0, %1}, %2;" : "=f"(lo), "=f"(hi) : "l"(v));
}
__device__ __forceinline__ void ffma2(unsigned long long& d,
                                      unsigned long long a, unsigned long long b) {
    asm("fma.rn.f32x2 %0, %1, %2, %0;" : "+l"(d) : "l"(a), "l"(b));
}
template <int K>
__device__ __forceinline__ void warp_gemm2(const float* __restrict__ sW,
                                           const float* __restrict__ sX,
                                           int j0, unsigned long long accp[4][2]) {
#pragma unroll 4
    for (int k4 = 0; k4 < K / 4; ++k4) {
        float4 xv[4];
#pragma unroll
        for (int r = 0; r < 4; ++r)
            xv[r] = *(const float4*)(sX + r * K + k4 * 4);
#pragma unroll
        for (int kk = 0; kk < 4; ++kk) {
            ulonglong2 wv = *(const ulonglong2*)(sW + (k4 * 4 + kk) * HD + j0);
#pragma unroll
            for (int r = 0; r < 4; ++r) {
                float x = ((const float*)&xv[r])[kk];
                unsigned long long xp = pack2(x, x);
                ffma2(accp[r][0], xp, wv.x);
                ffma2(accp[r][1], xp, wv.y);
            }
        }
    }
}
template <int K>
__device__ __forceinline__ void stage4(float* sX, const float* __restrict__ gX,
                                       int n0, int lane) {
#pragma unroll
    for (int r = 0; r < 4; ++r) {
        int n = n0 + r;
#pragma unroll
        for (int c0 = 0; c0 < K; c0 += 128) {
            int c = c0 + lane * 4;
            if (c < K) {
                float4 v = (n < NN) ? *(const float4*)(gX + (size_t)n * K + c)
                                    : make_float4(0.f, 0.f, 0.f, 0.f);
                *(float4*)(sX + r * K + c) = v;
            }
        }
    }
}

// =========================== CSR build =====================================
__global__ void zero_int_kernel(int* p, int n) {
    int i = blockIdx.x * blockDim.x + threadIdx.x;
    if (i < n) p[i] = 0;
}
__global__ void count_kernel(const int* __restrict__ dst, int* cnt) {
    int e = blockIdx.x * blockDim.x + threadIdx.x;
    if (e < NE) atomicAdd(&cnt[dst[e]], 1);
}
__global__ void scan_kernel(const int* __restrict__ cnt, int* rowptr) {
    __shared__ int ssum[1024];
    int t = threadIdx.x;
    const int CH = (NN + 1023) / 1024;
    int b0 = t * CH;
    int s = 0;
    for (int i = 0; i < CH; ++i)
        if (b0 + i < NN) s += cnt[b0 + i];
    ssum[t] = s;
    __syncthreads();
    for (int off = 1; off < 1024; off <<= 1) {
        int v = (t >= off) ? ssum[t - off] : 0;
        __syncthreads();
        ssum[t] += v;
        __syncthreads();
    }
    int run = (t > 0) ? ssum[t - 1] : 0;
    for (int i = 0; i < CH; ++i) {
        if (b0 + i < NN) {
            rowptr[b0 + i] = run;
            run += cnt[b0 + i];
        }
    }
    if (t == 1023) rowptr[NN] = run;
}
__global__ void fill_kernel(const int* __restrict__ src, const int* __restrict__ dst,
                            const int* __restrict__ rowptr, int* cur, int* adj) {
    int e = blockIdx.x * blockDim.x + threadIdx.x;
    if (e < NE) {
        int d = dst[e];
        int pos = atomicAdd(&cur[d], 1);
        adj[rowptr[d] + pos] = src[e];
    }
}

// =========================== encoder (fp32) ================================
__global__ __launch_bounds__(256, 2) void encode_kernel(
    const float* __restrict__ x, const float* __restrict__ W1,
    const float* __restrict__ b1, const float* __restrict__ W2,
    const float* __restrict__ b2, float* __restrict__ out) {
    extern __shared__ float sm[];
    float* sW1 = sm;
    float* sW2 = sW1 + 16 * HD;
    float* sb1 = sW2 + HD * HD;
    float* sb2 = sb1 + HD;
    float* sXall = sb2 + HD;
    float* sHall = sXall + 8 * 4 * 16;

    for (int i = threadIdx.x; i < 16 * HD / 4; i += blockDim.x)
        ((float4*)sW1)[i] = ((const float4*)W1)[i];
    for (int i = threadIdx.x; i < HD * HD / 4; i += blockDim.x)
        ((float4*)sW2)[i] = ((const float4*)W2)[i];
    if (threadIdx.x < HD) {
        sb1[threadIdx.x] = b1[threadIdx.x];
        sb2[threadIdx.x] = b2[threadIdx.x];
    }
    __syncthreads();

    int warp = threadIdx.x >> 5, lane = threadIdx.x & 31, j0 = lane * 4;
    float* sX = sXall + warp * 4 * 16;
    float* sH = sHall + warp * 4 * HD;

    unsigned long long bp1_0 = pack2(sb1[j0], sb1[j0 + 1]);
    unsigned long long bp1_1 = pack2(sb1[j0 + 2], sb1[j0 + 3]);
    unsigned long long bp2_0 = pack2(sb2[j0], sb2[j0 + 1]);
    unsigned long long bp2_1 = pack2(sb2[j0 + 2], sb2[j0 + 3]);

    for (int nb = blockIdx.x; nb * 32 < NN; nb += gridDim.x) {
        int n0 = nb * 32 + warp * 4;
        stage4<16>(sX, x, n0, lane);
        __syncwarp();
        unsigned long long accp[4][2];
#pragma unroll
        for (int r = 0; r < 4; ++r) { accp[r][0] = bp1_0; accp[r][1] = bp1_1; }
        warp_gemm2<16>(sW1, sX, j0, accp);
#pragma unroll
        for (int r = 0; r < 4; ++r) {
            float a0, a1, a2, a3;
            unpack2(accp[r][0], a0, a1);
            unpack2(accp[r][1], a2, a3);
            float4 o;
            o.x = gelu_f(a0); o.y = gelu_f(a1);
            o.z = gelu_f(a2); o.w = gelu_f(a3);
            *(float4*)(sH + r * HD + j0) = o;
        }
        __syncwarp();
        unsigned long long acc2[4][2];
#pragma unroll
        for (int r = 0; r < 4; ++r) { acc2[r][0] = bp2_0; acc2[r][1] = bp2_1; }
        warp_gemm2<128>(sW2, sH, j0, acc2);
#pragma unroll
        for (int r = 0; r < 4; ++r) {
            int n = n0 + r;
            if (n < NN) {
                float4 o;
                unpack2(acc2[r][0], o.x, o.y);
                unpack2(acc2[r][1], o.z, o.w);
                *(float4*)(out + (size_t)n * HD + j0) = o;
            }
        }
        __syncwarp();
    }
}

// =========================== CSR edge pass =================================
__global__ __launch_bounds__(256) void edge_csr_kernel(
    const int* __restrict__ rowptr, const int* __restrict__ adj,
    const float* __restrict__ A, const float* __restrict__ B,
    float* __restrict__ G) {
    int t = blockIdx.x * blockDim.x + threadIdx.x;
    int lane = t & 31;
    int c = lane * 4;
    int nwarps = (gridDim.x * blockDim.x) >> 5;
    for (int n = t >> 5; n < NN; n += nwarps) {
        int beg = __ldg(&rowptr[n]), end = __ldg(&rowptr[n + 1]);
        float4 b = __ldg((const float4*)(B + (size_t)n * HD + c));
        float4 g = make_float4(0.f, 0.f, 0.f, 0.f);
        for (int i = beg; i < end; i += 32) {
            int m = min(32, end - i);
            int s = (i + lane < end) ? __ldg(&adj[i + lane]) : 0;
#pragma unroll 8
            for (int k = 0; k < m; ++k) {
                int sk = __shfl_sync(0xffffffff, s, k);
                float4 a = *(const float4*)(A + (size_t)sk * HD + c);
                g.x += gelu_f(a.x + b.x);
                g.y += gelu_f(a.y + b.y);
                g.z += gelu_f(a.z + b.z);
                g.w += gelu_f(a.w + b.w);
            }
        }
        __stcg((float4*)(G + (size_t)n * HD + c), g);
    }
}

// ================= per-layer weight fold: M = eW2 @ nW1_bot ================
__global__ void prepM_kernel(const float* __restrict__ eW2,
                             const float* __restrict__ eb2,
                             const float* __restrict__ nW1,
                             float* __restrict__ M, float* __restrict__ v) {
    int idx = blockIdx.x * blockDim.x + threadIdx.x;
    int i = idx >> 7, j = idx & 127;
    float s = 0.f;
#pragma unroll 8
    for (int k = 0; k < HD; ++k)
        s += eW2[i * HD + k] * nW1[(size_t)(HD + k) * HD + j];
    M[idx] = s;
    if (i == 0) {
        float sv = 0.f;
#pragma unroll 8
        for (int k = 0; k < HD; ++k)
            sv += eb2[k] * nW1[(size_t)(HD + k) * HD + j];
        v[j] = sv;
    }
}

// =========================== decoder (fp32) ================================
__global__ __launch_bounds__(256, 2) void decode_kernel(
    const float* __restrict__ h, const float* __restrict__ W1,
    const float* __restrict__ b1, const float* __restrict__ W2,
    const float* __restrict__ b2, float* __restrict__ out) {
    extern __shared__ float sm[];
    float* sW1 = sm;
    float* sb1 = sW1 + HD * HD;
    float* sW2 = sb1 + HD;
    float* sb2 = sW2 + HD * 8;
    float* sXall = sb2 + 8;
    float* sHall = sXall + 8 * 4 * HD;

    for (int i = threadIdx.x; i < HD * HD / 4; i += blockDim.x)
        ((float4*)sW1)[i] = ((const float4*)W1)[i];
    for (int i = threadIdx.x; i < HD * 8 / 4; i += blockDim.x)
        ((float4*)sW2)[i] = ((const float4*)W2)[i];
    if (threadIdx.x < HD) sb1[threadIdx.x] = b1[threadIdx.x];
    if (threadIdx.x < 8) sb2[threadIdx.x] = b2[threadIdx.x];
    __syncthreads();

    int warp = threadIdx.x >> 5, lane = threadIdx.x & 31, j0 = lane * 4;
    float* sX = sXall + warp * 4 * HD;
    float* sH = sHall + warp * 4 * HD;
    unsigned long long bp0 = pack2(sb1[j0], sb1[j0 + 1]);
    unsigned long long bp1 = pack2(sb1[j0 + 2], sb1[j0 + 3]);

    for (int nb = blockIdx.x; nb * 32 < NN; nb += gridDim.x) {
        int n0 = nb * 32 + warp * 4;
        stage4<128>(sX, h, n0, lane);
        __syncwarp();
        unsigned long long accp[4][2];
#pragma unroll
        for (int r = 0; r < 4; ++r) { accp[r][0] = bp0; accp[r][1] = bp1; }
        warp_gemm2<128>(sW1, sX, j0, accp);
#pragma unroll
        for (int r = 0; r < 4; ++r) {
            float a0, a1, a2, a3;
            unpack2(accp[r][0], a0, a1);
            unpack2(accp[r][1], a2, a3);
            float4 o = make_float4(gelu_f(a0), gelu_f(a1), gelu_f(a2), gelu_f(a3));
            *(float4*)(sH + r * HD + j0) = o;
        }
        __syncwarp();
        int r = lane >> 3, o = lane & 7;
        float s = sb2[o];
#pragma unroll 8
        for (int k = 0; k < HD; ++k)
            s += sH[r * HD + k] * sW2[k * 8 + o];
        int n = n0 + r;
        if (n < NN) out[(size_t)n * 8 + o] = s;
        __syncwarp();
    }
}

// =========================== host launcher =================================
extern "C" void kernel_launch(void* const* d_in, const int* in_sizes, int n_in,
                              void* d_out, int out_size) {
    const float* x     = (const float*)d_in[0];
    const int*   ei    = (const int*)d_in[1];
    const float* encW1 = (const float*)d_in[2];
    const float* encb1 = (const float*)d_in[3];
    const float* encW2 = (const float*)d_in[4];
    const float* encb2 = (const float*)d_in[5];
    const float* eW1   = (const float*)d_in[6];
    const float* eb1   = (const float*)d_in[7];
    const float* eW2   = (const float*)d_in[8];
    const float* eb2   = (const float*)d_in[9];
    const float* nW1   = (const float*)d_in[10];
    const float* nb1   = (const float*)d_in[11];
    const float* nW2   = (const float*)d_in[12];
    const float* nb2   = (const float*)d_in[13];
    const float* dW1   = (const float*)d_in[14];
    const float* db1   = (const float*)d_in[15];
    const float* dW2   = (const float*)d_in[16];
    const float* db2   = (const float*)d_in[17];
    float* out = (float*)d_out;

    float *p_h, *p_A, *p_B, *p_G, *p_tmp, *p_M, *p_v, *p_zero;
    int *p_rowptr, *p_cnt, *p_adj;
    cudaGetSymbolAddress((void**)&p_h, g_h);
    cudaGetSymbolAddress((void**)&p_A, g_A);
    cudaGetSymbolAddress((void**)&p_B, g_B);
    cudaGetSymbolAddress((void**)&p_G, g_G);
    cudaGetSymbolAddress((void**)&p_tmp, g_tmp);
    cudaGetSymbolAddress((void**)&p_M, g_M);
    cudaGetSymbolAddress((void**)&p_v, g_v);
    cudaGetSymbolAddress((void**)&p_zero, g_zero);
    cudaGetSymbolAddress((void**)&p_rowptr, g_rowptr);
    cudaGetSymbolAddress((void**)&p_cnt, g_cnt);
    cudaGetSymbolAddress((void**)&p_adj, g_adj);

    const int SM_ENC = (16 * HD + HD * HD + 2 * HD + 8 * 4 * 16 + 8 * 4 * HD) * 4;
    const int SM_DEC = (HD * HD + HD + HD * 8 + 8 + 2 * 8 * 4 * HD) * 4;
    const int SM_MM1 = 1 * 2 * 128 * WSTRIDE * 2 + 2 * HD * 4;   // ~70.7 KB
    const int SM_MM2 = 2 * 2 * 128 * WSTRIDE * 2 + 2 * HD * 4;   // ~140.3 KB

    cudaFuncSetAttribute(encode_kernel, cudaFuncAttributeMaxDynamicSharedMemorySize, SM_ENC);
    cudaFuncSetAttribute(decode_kernel, cudaFuncAttributeMaxDynamicSharedMemorySize, SM_DEC);
    cudaFuncSetAttribute(mma_gemm_kernel<1, 0>, cudaFuncAttributeMaxDynamicSharedMemorySize, SM_MM1);
    cudaFuncSetAttribute(mma_gemm_kernel<1, 2>, cudaFuncAttributeMaxDynamicSharedMemorySize, SM_MM1);
    cudaFuncSetAttribute(mma_gemm_kernel<2, 1>, cudaFuncAttributeMaxDynamicSharedMemorySize, SM_MM2);

    // ---- build dst-CSR ----
    zero_int_kernel<<<(NN + 255) / 256, 256>>>(p_cnt, NN);
    count_kernel<<<(NE + 255) / 256, 256>>>(ei + NE, p_cnt);
    scan_kernel<<<1, 1024>>>(p_cnt, p_rowptr);
    zero_int_kernel<<<(NN + 255) / 256, 256>>>(p_cnt, NN);
    fill_kernel<<<(NE + 255) / 256, 256>>>(ei, ei + NE, p_rowptr, p_cnt, p_adj);

    encode_kernel<<<304, 256, SM_ENC>>>(x, encW1, encb1, encW2, encb2, p_h);

    for (int l = 0; l < NL; ++l) {
        prepM_kernel<<<64, 256>>>(eW2 + (size_t)l * HD * HD, eb2 + l * HD,
                                  nW1 + (size_t)l * 256 * HD, p_M, p_v);
        // A = h @ eW1_top + eb1
        mma_gemm_kernel<1, 0><<<148, 256, SM_MM1>>>(
            p_h, eW1 + (size_t)l * 256 * HD, nullptr, nullptr,
            eb1 + l * HD, p_zero, p_rowptr, p_A);
        // B = h @ eW1_bot
        mma_gemm_kernel<1, 0><<<148, 256, SM_MM1>>>(
            p_h, eW1 + (size_t)l * 256 * HD + HD * HD, nullptr, nullptr,
            p_zero, p_zero, p_rowptr, p_B);
        edge_csr_kernel<<<2368, 256>>>(p_rowptr, p_adj, p_A, p_B, p_G);
        // tmp = gelu(h @ nW1_top + G @ M + deg*v + nb1)
        mma_gemm_kernel<2, 1><<<148, 256, SM_MM2>>>(
            p_h, nW1 + (size_t)l * 256 * HD, p_G, p_M,
            nb1 + l * HD, p_v, p_rowptr, p_tmp);
        // h += tmp @ nW2 + nb2
        mma_gemm_kernel<1, 2><<<148, 256, SM_MM1>>>(
            p_tmp, nW2 + (size_t)l * HD * HD, nullptr, nullptr,
            nb2 + l * HD, p_zero, p_rowptr, p_h);
    }

    decode_kernel<<<304, 256, SM_DEC>>>(p_h, dW1, db1, dW2, db2, out);
}